// round 1
// baseline (speedup 1.0000x reference)
#include <cuda_runtime.h>
#include <cuda_bf16.h>

// L1OrderLoss (Chamfer-style L1, PTS_DIM=2): pred/target [8192,128] f32.
// Rows are independent: 64 points x 2 coords per row.
// loss = mean over [N, P*2] of 0.5*(dist_1 + dist_2) / num_pts (=64)
//   dist_1[i,c] = min_j |p[i,c] - t[j,c]|   (per coordinate!)
//   dist_2[j,c] = min_i |p[i,c] - t[j,c]|

#define NROWS   8192
#define PPTS    64           // points per row
#define ROWS_PER_BLOCK 4
#define THREADS (ROWS_PER_BLOCK * PPTS)   // 256

// final scale: 0.5 (chamfer avg) * 1/(N*P*2) (mean) * 1/64 (num_pts)
#define OUT_SCALE (0.5f / (8192.0f * 128.0f * 64.0f))

__global__ void zero_out_kernel(float* out) {
    out[0] = 0.0f;
}

__global__ __launch_bounds__(THREADS, 8)
void l1order_kernel(const float* __restrict__ pred,
                    const float* __restrict__ target,
                    float* __restrict__ out)
{
    __shared__ float2 ps[ROWS_PER_BLOCK][PPTS];
    __shared__ float2 ts[ROWS_PER_BLOCK][PPTS];
    __shared__ float  warp_sums[THREADS / 32];

    const int tid = threadIdx.x;
    const int r   = tid >> 6;        // local row 0..3
    const int k   = tid & 63;        // point index within row
    const int row = blockIdx.x * ROWS_PER_BLOCK + r;

    // Each row = 128 floats = 64 float2. Thread k loads point k of pred & target.
    const float2* predv   = reinterpret_cast<const float2*>(pred);
    const float2* targetv = reinterpret_cast<const float2*>(target);
    float2 p = predv[row * PPTS + k];
    float2 t = targetv[row * PPTS + k];
    ps[r][k] = p;
    ts[r][k] = t;
    __syncthreads();

    // dist_1 for pred point k (min over target points),
    // dist_2 for target point k (min over pred points), per coordinate.
    float d1x = 1e30f, d1y = 1e30f, d2x = 1e30f, d2y = 1e30f;

    #pragma unroll 8
    for (int j = 0; j < PPTS; ++j) {
        float2 tj = ts[r][j];   // broadcast within row's 2 warps
        float2 pj = ps[r][j];
        d1x = fminf(d1x, fabsf(p.x - tj.x));
        d1y = fminf(d1y, fabsf(p.y - tj.y));
        d2x = fminf(d2x, fabsf(pj.x - t.x));
        d2y = fminf(d2y, fabsf(pj.y - t.y));
    }

    float s = (d1x + d1y) + (d2x + d2y);

    // warp reduce
    #pragma unroll
    for (int off = 16; off > 0; off >>= 1)
        s += __shfl_down_sync(0xFFFFFFFFu, s, off);

    const int wid = tid >> 5;
    if ((tid & 31) == 0) warp_sums[wid] = s;
    __syncthreads();

    if (wid == 0) {
        float v = (tid < (THREADS / 32)) ? warp_sums[tid] : 0.0f;
        #pragma unroll
        for (int off = 4; off > 0; off >>= 1)
            v += __shfl_down_sync(0xFFFFFFFFu, v, off);
        if (tid == 0)
            atomicAdd(out, v * OUT_SCALE);
    }
}

extern "C" void kernel_launch(void* const* d_in, const int* in_sizes, int n_in,
                              void* d_out, int out_size)
{
    const float* pred   = (const float*)d_in[0];
    const float* target = (const float*)d_in[1];
    float* out = (float*)d_out;

    zero_out_kernel<<<1, 1>>>(out);
    l1order_kernel<<<NROWS / ROWS_PER_BLOCK, THREADS>>>(pred, target, out);
}

// round 2
// speedup vs baseline: 1.1338x; 1.1338x over previous
#include <cuda_runtime.h>
#include <cuda_bf16.h>

// L1OrderLoss (Chamfer-style L1, PTS_DIM=2): pred/target [8192,128] f32.
// Per row (64 2-D points): dist_1[i,c]=min_j|p[i,c]-t[j,c]|, dist_2[j,c]=min_i|.|
// out = 0.5*(sum dist_1 + sum dist_2) / (N*P*2) / 64
//
// Issue-bound kernel: minimize warp-instructions per pair.
//  - targets staged NEGATED in shared -> diff via add.rn.f32x2 (1 instr for both coords)
//  - shared read as float4 (1 LDS.128 per 2 points), broadcast across the row's threads
//  - fminf(acc, fabsf(d)) -> single FMNMX with |src| modifier

#define NROWS   8192
#define PPTS    64
#define RPB     4
#define THREADS (RPB * PPTS)   // 256

#define OUT_SCALE (0.5f / (8192.0f * 128.0f * 64.0f))

__global__ void zero_out_kernel(float* out) {
    out[0] = 0.0f;
}

// d = a + b on packed f32x2, expressed with float in/out so ptxas can alias
// the 64-bit pair onto the scalar registers (movs eliminated by allocation).
__device__ __forceinline__ void addx2(float ax, float ay, float bx, float by,
                                      float& rx, float& ry) {
    asm("{\n\t"
        ".reg .b64 ra, rb, rc;\n\t"
        "mov.b64 ra, {%2, %3};\n\t"
        "mov.b64 rb, {%4, %5};\n\t"
        "add.rn.f32x2 rc, ra, rb;\n\t"
        "mov.b64 {%0, %1}, rc;\n\t"
        "}"
        : "=f"(rx), "=f"(ry)
        : "f"(ax), "f"(ay), "f"(bx), "f"(by));
}

__global__ __launch_bounds__(THREADS, 8)
void l1order_kernel(const float* __restrict__ pred,
                    const float* __restrict__ target,
                    float* __restrict__ out)
{
    __shared__ __align__(16) float2 ps[RPB][PPTS];    // pred points
    __shared__ __align__(16) float2 nts[RPB][PPTS];   // NEGATED target points
    __shared__ float warp_sums[THREADS / 32];

    const int tid = threadIdx.x;
    const int r   = tid >> 6;        // local row 0..3
    const int k   = tid & 63;        // point index within row
    const int row = blockIdx.x * RPB + r;

    const float2* predv   = reinterpret_cast<const float2*>(pred);
    const float2* targetv = reinterpret_cast<const float2*>(target);
    float2 p  = predv[row * PPTS + k];
    float2 t  = targetv[row * PPTS + k];
    float ntx = -t.x, nty = -t.y;    // thread's own negated target
    ps[r][k]  = p;
    nts[r][k] = make_float2(ntx, nty);
    __syncthreads();

    float d1x = 1e30f, d1y = 1e30f, d2x = 1e30f, d2y = 1e30f;

    const float4* psv = reinterpret_cast<const float4*>(&ps[r][0]);
    const float4* ntv = reinterpret_cast<const float4*>(&nts[r][0]);

    // PAIR: one target point (negated: nx,ny) and one pred point (px,py)
    //   d1 update: |p_k - t_j|    = | p + nt_j |
    //   d2 update: |p_j - t_k|    = | p_j + nt_k |
#define PAIR(nx, ny, px, py)                              \
    do {                                                  \
        float ax, ay, bx, by;                             \
        addx2(p.x, p.y, (nx), (ny), ax, ay);              \
        addx2((px), (py), ntx, nty, bx, by);              \
        d1x = fminf(d1x, fabsf(ax));                      \
        d1y = fminf(d1y, fabsf(ay));                      \
        d2x = fminf(d2x, fabsf(bx));                      \
        d2y = fminf(d2y, fabsf(by));                      \
    } while (0)

    #pragma unroll 4
    for (int c = 0; c < PPTS / 4; ++c) {
        float4 t01 = ntv[2 * c];        // neg targets 4c, 4c+1
        float4 t23 = ntv[2 * c + 1];    // neg targets 4c+2, 4c+3
        float4 p01 = psv[2 * c];        // preds 4c, 4c+1
        float4 p23 = psv[2 * c + 1];
        PAIR(t01.x, t01.y, p01.x, p01.y);
        PAIR(t01.z, t01.w, p01.z, p01.w);
        PAIR(t23.x, t23.y, p23.x, p23.y);
        PAIR(t23.z, t23.w, p23.z, p23.w);
    }
#undef PAIR

    float s = (d1x + d1y) + (d2x + d2y);

    #pragma unroll
    for (int off = 16; off > 0; off >>= 1)
        s += __shfl_down_sync(0xFFFFFFFFu, s, off);

    const int wid = tid >> 5;
    if ((tid & 31) == 0) warp_sums[wid] = s;
    __syncthreads();

    if (wid == 0) {
        float v = (tid < (THREADS / 32)) ? warp_sums[tid] : 0.0f;
        #pragma unroll
        for (int off = 4; off > 0; off >>= 1)
            v += __shfl_down_sync(0xFFFFFFFFu, v, off);
        if (tid == 0)
            atomicAdd(out, v * OUT_SCALE);
    }
}

extern "C" void kernel_launch(void* const* d_in, const int* in_sizes, int n_in,
                              void* d_out, int out_size)
{
    const float* pred   = (const float*)d_in[0];
    const float* target = (const float*)d_in[1];
    float* out = (float*)d_out;

    zero_out_kernel<<<1, 1>>>(out);
    l1order_kernel<<<NROWS / RPB, THREADS>>>(pred, target, out);
}

// round 3
// speedup vs baseline: 1.1509x; 1.0151x over previous
#include <cuda_runtime.h>
#include <cuda_bf16.h>

// L1OrderLoss (Chamfer-style L1, PTS_DIM=2): pred/target [8192,128] f32.
// Per row (64 2-D points): dist_1[i,c]=min_j|p[i,c]-t[j,c]|, dist_2[j,c]=min_i|.|
// out = 0.5*(sum d1 + sum d2) / (N*P*2) / 64
//
// Packed-f32x2 kernel with ZERO pack movs:
//  - own pred point and own negated target packed into b64 once
//  - shared tiles read as ulonglong2 (LDS.128 = 2 packed points)
//  - diff via add.rn.f32x2 directly on b64 operands
//  - fminf(acc, fabsf(.)) -> single FMNMX with |src|

#define NROWS   8192
#define PPTS    64
#define RPB     4
#define THREADS (RPB * PPTS)   // 256

#define OUT_SCALE (0.5f / (8192.0f * 128.0f * 64.0f))

__global__ void zero_out_kernel(float* out) {
    out[0] = 0.0f;
}

// rc = a + b (packed f32x2); only an unpack mov remains, which ptxas
// eliminates via register-pair allocation.
__device__ __forceinline__ void addx2p(unsigned long long a, unsigned long long b,
                                       float& rx, float& ry) {
    asm("{\n\t"
        ".reg .b64 rc;\n\t"
        "add.rn.f32x2 rc, %2, %3;\n\t"
        "mov.b64 {%0, %1}, rc;\n\t"
        "}"
        : "=f"(rx), "=f"(ry)
        : "l"(a), "l"(b));
}

__global__ __launch_bounds__(THREADS)
void l1order_kernel(const float* __restrict__ pred,
                    const float* __restrict__ target,
                    float* __restrict__ out)
{
    __shared__ __align__(16) float2 ps[RPB][PPTS];    // pred points
    __shared__ __align__(16) float2 nts[RPB][PPTS];   // NEGATED target points
    __shared__ float warp_sums[THREADS / 32];

    const int tid = threadIdx.x;
    const int r   = tid >> 6;        // local row 0..3
    const int k   = tid & 63;        // point index within row
    const int row = blockIdx.x * RPB + r;

    const float2* predv   = reinterpret_cast<const float2*>(pred);
    const float2* targetv = reinterpret_cast<const float2*>(target);
    float2 p = predv[row * PPTS + k];
    float2 t = targetv[row * PPTS + k];
    float ntx = -t.x, nty = -t.y;
    ps[r][k]  = p;
    nts[r][k] = make_float2(ntx, nty);

    // Pack own pred point and own negated target into b64 (once).
    unsigned long long pk, ntk;
    asm("mov.b64 %0, {%1, %2};" : "=l"(pk)  : "f"(p.x), "f"(p.y));
    asm("mov.b64 %0, {%1, %2};" : "=l"(ntk) : "f"(ntx), "f"(nty));

    __syncthreads();

    float d1x = 1e30f, d1y = 1e30f, d2x = 1e30f, d2y = 1e30f;

    const ulonglong2* psv = reinterpret_cast<const ulonglong2*>(&ps[r][0]);
    const ulonglong2* ntv = reinterpret_cast<const ulonglong2*>(&nts[r][0]);

    // PAIR(ntj, pj): point j's negated target (packed) and pred (packed).
    //   d1 update: |p_k - t_j| = |pk + ntj|
    //   d2 update: |p_j - t_k| = |pj + ntk|
#define PAIR(ntj, pj)                                     \
    do {                                                  \
        float ax, ay, bx, by;                             \
        addx2p(pk, (ntj), ax, ay);                        \
        addx2p((pj), ntk, bx, by);                        \
        d1x = fminf(d1x, fabsf(ax));                      \
        d1y = fminf(d1y, fabsf(ay));                      \
        d2x = fminf(d2x, fabsf(bx));                      \
        d2y = fminf(d2y, fabsf(by));                      \
    } while (0)

    #pragma unroll
    for (int c = 0; c < PPTS / 2; ++c) {   // 2 points per iteration
        ulonglong2 tt = ntv[c];   // neg targets 2c, 2c+1 (one LDS.128)
        ulonglong2 pp = psv[c];   // preds       2c, 2c+1 (one LDS.128)
        PAIR(tt.x, pp.x);
        PAIR(tt.y, pp.y);
    }
#undef PAIR

    float s = (d1x + d1y) + (d2x + d2y);

    #pragma unroll
    for (int off = 16; off > 0; off >>= 1)
        s += __shfl_down_sync(0xFFFFFFFFu, s, off);

    const int wid = tid >> 5;
    if ((tid & 31) == 0) warp_sums[wid] = s;
    __syncthreads();

    if (wid == 0) {
        float v = (tid < (THREADS / 32)) ? warp_sums[tid] : 0.0f;
        #pragma unroll
        for (int off = 4; off > 0; off >>= 1)
            v += __shfl_down_sync(0xFFFFFFFFu, v, off);
        if (tid == 0)
            atomicAdd(out, v * OUT_SCALE);
    }
}

extern "C" void kernel_launch(void* const* d_in, const int* in_sizes, int n_in,
                              void* d_out, int out_size)
{
    const float* pred   = (const float*)d_in[0];
    const float* target = (const float*)d_in[1];
    float* out = (float*)d_out;

    zero_out_kernel<<<1, 1>>>(out);
    l1order_kernel<<<NROWS / RPB, THREADS>>>(pred, target, out);
}